// round 8
// baseline (speedup 1.0000x reference)
#include <cuda_runtime.h>
#include <cstdint>

// ============================================================================
// BinaryLinearWscales (GB300, compute_103: SIMT only; mma.sync is emulated).
//   out[m,n] = wscale[n]*(x @ sign(W)^T)[m,n] + wbias[n]*rowsum(x)[m]
// Dual-pipe: T = round(x*2032/rowmax) = 16*q1 + (u-8), q1 s8, u in [0,15].
//   fma pipe: dp4a(q1_bytes, (16*s)_bytes) + IMAD for 2 plane accums
//   alu pipe: AND+POPC (+LEA) for 4 bitplanes
//   sum(T*s) = ACC - B1[m] - 8*Sn[n]
// Pipeline: cp.async.cg, 3 buffers, RACE-FREE ordering:
//   wait_group -> __syncthreads -> issue(ch+2) -> compute(ch)
// ============================================================================

// ---------------- device scratch ----------------------------------------------
__device__ __align__(16384) int8_t   g_q1[16777216];   // 16 MB q1 bytes (swizzled)
__device__ __align__(16384) int8_t   g_bs[16777216];   // 16 MB 16*sign bytes (swizzled)
__device__ __align__(16384) uint32_t g_pl[2097152];    //  8 MB u bitplanes
__device__ __align__(16384) uint32_t g_sp[524288];     //  2 MB sign masks
__device__ float g_alpha [4096];                       // rowmax/2032
__device__ float g_rowsum[4096];
__device__ int   g_B1    [4096];                       // sum_k u
__device__ int   g_Sn    [4096];                       // sum_k sign

// ---------------- helpers -------------------------------------------------------
static __device__ __forceinline__ uint32_t smem_u32(const void* p) {
    uint32_t a;
    asm("{ .reg .u64 t; cvta.to.shared.u64 t, %1; cvt.u32.u64 %0, t; }" : "=r"(a) : "l"(p));
    return a;
}
static __device__ __forceinline__ void cpa16(uint32_t dst, const void* src) {
    asm volatile("cp.async.cg.shared.global [%0], [%1], 16;" :: "r"(dst), "l"(src));
}
#define CP_COMMIT() asm volatile("cp.async.commit_group;" ::: "memory")

// ---------------- geometry -------------------------------------------------------
static constexpr int      NCHUNK   = 32;        // k-chunks of 128
static constexpr uint32_t QB_B     = 16384;     // 128 rows x 128 bytes per chunk
static constexpr uint32_t PL_B     = 8192;      // 4 kb x 4 planes x 128 rows x 4B
static constexpr uint32_t SP_B     = 2048;      // 4 kb x 128 rows x 4B
static constexpr uint32_t OFF_BS   = 16384;
static constexpr uint32_t OFF_PL   = 32768;
static constexpr uint32_t OFF_SP   = 40960;
static constexpr uint32_t BUF_B    = 43008;     // one stage
static constexpr uint32_t SMEM_DYN = 3 * BUF_B; // 129024

// ---------------- prologue: quantize x ------------------------------------------
__global__ void __launch_bounds__(128) prep_x_kernel(const float* __restrict__ x) {
    const int m = blockIdx.x;
    const int tid = threadIdx.x;
    const float* src = x + (size_t)m * 4096 + tid * 32;

    float f[32];
    #pragma unroll
    for (int i = 0; i < 8; i++) {
        float4 v = ((const float4*)src)[i];
        f[4*i] = v.x; f[4*i+1] = v.y; f[4*i+2] = v.z; f[4*i+3] = v.w;
    }

    __shared__ float s_mx[128], s_sm[128];
    __shared__ int   s_u[128];
    float mx = 0.f, sm = 0.f;
    #pragma unroll
    for (int i = 0; i < 32; i++) { mx = fmaxf(mx, fabsf(f[i])); sm += f[i]; }
    s_mx[tid] = mx; s_sm[tid] = sm;
    __syncthreads();
    for (int s = 64; s > 0; s >>= 1) {
        if (tid < s) {
            s_mx[tid] = fmaxf(s_mx[tid], s_mx[tid + s]);
            s_sm[tid] += s_sm[tid + s];
        }
        __syncthreads();
    }
    const float maxv = s_mx[0];
    const float inv  = (maxv > 0.f) ? 2032.f / maxv : 0.f;

    uint32_t qw[8] = {0,0,0,0,0,0,0,0};
    uint32_t t0 = 0, t1 = 0, t2 = 0, t3 = 0;
    int usum = 0;
    #pragma unroll
    for (int e = 0; e < 32; e++) {
        int T  = __float2int_rn(f[e] * inv);
        int tp = T + 8;
        int q1 = tp >> 4;          // [-127,127]
        int u  = tp & 15;          // [0,15]
        usum += u;
        qw[e >> 2] |= (uint32_t)(q1 & 0xff) << ((e & 3) * 8);
        t0 |= (uint32_t)(u & 1)        << e;
        t1 |= (uint32_t)((u >> 1) & 1) << e;
        t2 |= (uint32_t)((u >> 2) & 1) << e;
        t3 |= (uint32_t)((u >> 3) & 1) << e;
    }
    s_u[tid] = usum;
    __syncthreads();
    for (int s = 64; s > 0; s >>= 1) {
        if (tid < s) s_u[tid] += s_u[tid + s];
        __syncthreads();
    }

    const int chunk = tid >> 2, kb = tid & 3;
    const int r = m & 127;
    const uint32_t swz = (uint32_t)((r & 7) * 16);
    char* qb = (char*)g_q1 + (size_t)((m >> 7) * 32 + chunk) * QB_B + (size_t)r * 128;
    #pragma unroll
    for (int e8 = 0; e8 < 8; e8++)
        *(uint32_t*)(qb + (((uint32_t)(kb * 32 + e8 * 4)) ^ swz)) = qw[e8];

    uint32_t* pb = g_pl + (size_t)((m >> 7) * 32 + chunk) * 2048 + (size_t)kb * 512 + r;
    pb[0] = t0; pb[128] = t1; pb[256] = t2; pb[384] = t3;

    if (tid == 0) {
        g_alpha[m]  = (maxv > 0.f) ? maxv / 2032.f : 0.f;
        g_rowsum[m] = s_sm[0];
        g_B1[m]     = s_u[0];
    }
}

// ---------------- prologue: sign(W) ----------------------------------------------
__global__ void __launch_bounds__(128) prep_w_kernel(const float* __restrict__ w) {
    const int n = blockIdx.x;
    const int tid = threadIdx.x;
    const float* src = w + (size_t)n * 4096 + tid * 32;

    float f[32];
    #pragma unroll
    for (int i = 0; i < 8; i++) {
        float4 v = ((const float4*)src)[i];
        f[4*i] = v.x; f[4*i+1] = v.y; f[4*i+2] = v.z; f[4*i+3] = v.w;
    }

    uint32_t qw[8] = {0,0,0,0,0,0,0,0};
    uint32_t spw = 0;
    int sn = 0;
    #pragma unroll
    for (int e = 0; e < 32; e++) {
        float v = f[e];
        int b = (v > 0.f) ? 16 : ((v < 0.f) ? -16 : 0);
        sn += (v > 0.f) - (v < 0.f);
        qw[e >> 2] |= (uint32_t)(b & 0xff) << ((e & 3) * 8);
        spw |= (v > 0.f ? 1u : 0u) << e;
    }
    __shared__ int s_n[128];
    s_n[tid] = sn;
    __syncthreads();
    for (int s = 64; s > 0; s >>= 1) {
        if (tid < s) s_n[tid] += s_n[tid + s];
        __syncthreads();
    }

    const int chunk = tid >> 2, kb = tid & 3;
    const int r = n & 127;
    const uint32_t swz = (uint32_t)((r & 7) * 16);
    char* qb = (char*)g_bs + (size_t)((n >> 7) * 32 + chunk) * QB_B + (size_t)r * 128;
    #pragma unroll
    for (int e8 = 0; e8 < 8; e8++)
        *(uint32_t*)(qb + (((uint32_t)(kb * 32 + e8 * 4)) ^ swz)) = qw[e8];

    g_sp[(size_t)((n >> 7) * 32 + chunk) * 512 + (size_t)kb * 128 + r] = spw;
    if (tid == 0) g_Sn[n] = s_n[0];
}

// ---------------- stage loader ------------------------------------------------------
static __device__ __forceinline__ void issue_stage(
    uint32_t sb, int tid, int buf, int ch,
    const char* pQ, const char* pS, const char* pPL, const char* pSP) {
    const uint32_t d = sb + (uint32_t)buf * BUF_B;
    #pragma unroll
    for (int r = 0; r < 4; r++)
        cpa16(d + (uint32_t)(tid + 256 * r) * 16, pQ + (size_t)ch * QB_B + (tid + 256 * r) * 16);
    #pragma unroll
    for (int r = 0; r < 4; r++)
        cpa16(d + OFF_BS + (uint32_t)(tid + 256 * r) * 16, pS + (size_t)ch * QB_B + (tid + 256 * r) * 16);
    #pragma unroll
    for (int r = 0; r < 2; r++)
        cpa16(d + OFF_PL + (uint32_t)(tid + 256 * r) * 16, pPL + (size_t)ch * PL_B + (tid + 256 * r) * 16);
    if (tid < 128)
        cpa16(d + OFF_SP + (uint32_t)tid * 16, pSP + (size_t)ch * SP_B + tid * 16);
    CP_COMMIT();
}

// ---------------- main GEMM -----------------------------------------------------------
__global__ void __launch_bounds__(256, 1)
gemm_kernel(const float* __restrict__ wscale, const float* __restrict__ wbias,
            float* __restrict__ out) {
    extern __shared__ __align__(1024) char smem[];
    const uint32_t sb = smem_u32(smem);
    const int tid = threadIdx.x;
    const int g = tid & 15;
    const int h = tid >> 4;
    const int ntile = blockIdx.x;
    const int mtile = blockIdx.y;

    const char* pQ  = (const char*)g_q1 + (size_t)mtile * (32u * QB_B);
    const char* pS  = (const char*)g_bs + (size_t)ntile * (32u * QB_B);
    const char* pPL = (const char*)(g_pl + (size_t)mtile * (32u * 2048u));
    const char* pSP = (const char*)(g_sp + (size_t)ntile * (32u * 512u));

    issue_stage(sb, tid, 0, 0, pQ, pS, pPL, pSP);
    issue_stage(sb, tid, 1, 1, pQ, pS, pPL, pSP);

    const uint32_t aswz = (uint32_t)((g & 7) * 16);
    const uint32_t bswz = (uint32_t)((h & 7) * 16);

    int acc[8][8];
    #pragma unroll
    for (int i = 0; i < 8; i++)
        #pragma unroll
        for (int j = 0; j < 8; j++) acc[i][j] = 0;

    #pragma unroll 1
    for (int ch = 0; ch < NCHUNK; ch++) {
        // -------- RACE-FREE ordering: wait, sync, THEN issue into freed buffer ----
        if (ch + 1 < NCHUNK) { asm volatile("cp.async.wait_group 1;" ::: "memory"); }
        else                 { asm volatile("cp.async.wait_group 0;" ::: "memory"); }
        __syncthreads();   // all threads done computing chunk ch-1; stage ch visible
        if (ch + 2 < NCHUNK)
            issue_stage(sb, tid, (ch + 2) % 3, ch + 2, pQ, pS, pPL, pSP);

        const char* S  = smem + (uint32_t)(ch % 3) * BUF_B;
        const char* SA = S;
        const char* SB = S + OFF_BS;
        const uint32_t* PL = (const uint32_t*)(S + OFF_PL);
        const uint32_t* SP = (const uint32_t*)(S + OFF_SP);

        #pragma unroll 1
        for (int kb = 0; kb < 4; kb++) {
            // ---- alu stream: 4 bitplanes; 2 accums pinned to IMAD (fma pipe) ----
            uint32_t sp[8], pl[8][4];
            #pragma unroll
            for (int j = 0; j < 8; j++) sp[j] = SP[kb * 128 + h + 16 * j];
            #pragma unroll
            for (int i = 0; i < 8; i++) {
                const uint32_t* p = PL + kb * 512 + g + 16 * i;
                pl[i][0] = p[0]; pl[i][1] = p[128]; pl[i][2] = p[256]; pl[i][3] = p[384];
            }
            #pragma unroll
            for (int i = 0; i < 8; i++)
                #pragma unroll
                for (int j = 0; j < 8; j++) {
                    int p0 = __popc(pl[i][0] & sp[j]);
                    int p1 = __popc(pl[i][1] & sp[j]);
                    int p2 = __popc(pl[i][2] & sp[j]);
                    int p3 = __popc(pl[i][3] & sp[j]);
                    acc[i][j] += (p0 << 1) + (p1 << 2);          // alu (LEA chain)
                    asm("mad.lo.s32 %0, %1, 8, %0;"  : "+r"(acc[i][j]) : "r"(p2));  // fma
                    asm("mad.lo.s32 %0, %1, 16, %0;" : "+r"(acc[i][j]) : "r"(p3));  // fma
                }

            // ---- fma stream: dp4a on q1 x 16s ----
            #pragma unroll
            for (int sub = 0; sub < 2; sub++) {
                const uint32_t col = (uint32_t)(kb * 32 + sub * 16);
                int4 a4[8];
                #pragma unroll
                for (int i = 0; i < 8; i++)
                    a4[i] = *(const int4*)(SA + (g + 16 * i) * 128 + (col ^ aswz));
                #pragma unroll
                for (int jh = 0; jh < 2; jh++) {
                    int4 b4[4];
                    #pragma unroll
                    for (int jj = 0; jj < 4; jj++)
                        b4[jj] = *(const int4*)(SB + (h + 16 * (jh * 4 + jj)) * 128 + (col ^ bswz));
                    #pragma unroll
                    for (int i = 0; i < 8; i++)
                        #pragma unroll
                        for (int jj = 0; jj < 4; jj++) {
                            int* a = &acc[i][jh * 4 + jj];
                            *a = __dp4a(a4[i].x, b4[jj].x, *a);
                            *a = __dp4a(a4[i].y, b4[jj].y, *a);
                            *a = __dp4a(a4[i].z, b4[jj].z, *a);
                            *a = __dp4a(a4[i].w, b4[jj].w, *a);
                        }
                }
            }
        }
    }

    // ---------------- epilogue ----------------
    __syncthreads();
    float* fs = (float*)smem;   // 128 x 132 floats

    float alpha[8], rsum[8];
    int b1[8];
    #pragma unroll
    for (int i = 0; i < 8; i++) {
        int m = mtile * 128 + g + 16 * i;
        alpha[i] = g_alpha[m];
        rsum[i]  = g_rowsum[m];
        b1[i]    = g_B1[m];
    }
    float ws[8], wb[8];
    int sn8[8];
    #pragma unroll
    for (int j = 0; j < 8; j++) {
        int n = ntile * 128 + h + 16 * j;
        ws[j]  = __ldg(wscale + n);
        wb[j]  = __ldg(wbias + n);
        sn8[j] = 8 * g_Sn[n];
    }
    #pragma unroll
    for (int i = 0; i < 8; i++)
        #pragma unroll
        for (int j = 0; j < 8; j++) {
            int ts = acc[i][j] - b1[i] - sn8[j];
            fs[(g + 16 * i) * 132 + (h + 16 * j)] =
                ws[j] * (alpha[i] * (float)ts) + wb[j] * rsum[i];
        }
    __syncthreads();

    #pragma unroll 1
    for (int idx = tid; idx < 128 * 32; idx += 256) {
        int row = idx >> 5;
        int c4  = idx & 31;
        float4 v = *(const float4*)(fs + row * 132 + c4 * 4);
        *(float4*)(out + (size_t)(mtile * 128 + row) * 4096 + ntile * 128 + c4 * 4) = v;
    }
}

// ---------------- launch -----------------------------------------------------------------
extern "C" void kernel_launch(void* const* d_in, const int* in_sizes, int n_in,
                              void* d_out, int out_size) {
    (void)in_sizes; (void)n_in; (void)out_size;
    const float* x      = (const float*)d_in[0];   // [2,2048,4096]
    const float* weight = (const float*)d_in[1];   // [4096,4096]
    const float* wscale = (const float*)d_in[2];   // [4096,1]
    const float* wbias  = (const float*)d_in[3];   // [4096,1]
    float* out = (float*)d_out;

    cudaFuncSetAttribute(gemm_kernel, cudaFuncAttributeMaxDynamicSharedMemorySize,
                         (int)SMEM_DYN);

    prep_x_kernel<<<4096, 128>>>(x);
    prep_w_kernel<<<4096, 128>>>(weight);
    gemm_kernel<<<dim3(32, 32), 256, SMEM_DYN>>>(wscale, wbias, out);
}

// round 9
// speedup vs baseline: 1.3843x; 1.3843x over previous
#include <cuda_runtime.h>
#include <cuda_bf16.h>
#include <cstdint>

// ============================================================================
// BinaryLinearWscales (GB300, compute_103 -> mma.sync/dp4a SIMT floor).
//   out[m,n] = wscale[n] * (x @ sign(W)^T)[m,n] + wbias[n] * rowsum(x)[m]
// GEMM as 2-level int8: x ~= alpha_m * (q1 + q2/254), sign(W) exact in s8.
// mma.sync.m16n8k32.s8 (lowered to dp4a-class ops; runs at the SIMT int8
// issue floor, measured 1870us and matching the fma-pipe cycle model).
// This round: identical GEMM core to the proven R4 run; preps merged into
// one launch to overlap their DRAM phases.
// ============================================================================

// ---------------- device scratch (pre-swizzled tiled s8) --------------------
// Layout: [tile(128 rows)][kchunk(128 bytes)] -> 16KB tile, SW128 swizzled.
__device__ __align__(16384) int8_t g_a0[16777216];   // 16 MB: q1 of x
__device__ __align__(16384) int8_t g_a1[16777216];   // 16 MB: q2 of x
__device__ __align__(16384) int8_t g_b [16777216];   // 16 MB: sign(W)
__device__ float g_scale [4096];
__device__ float g_rowsum[4096];

// ---------------- PTX helpers ------------------------------------------------
static __device__ __forceinline__ uint32_t smem_u32(const void* p) {
    uint32_t a;
    asm("{ .reg .u64 t; cvta.to.shared.u64 t, %1; cvt.u32.u64 %0, t; }" : "=r"(a) : "l"(p));
    return a;
}

#define MBARRIER_INIT(addr, cnt) \
    asm volatile("mbarrier.init.shared.b64 [%0], %1;" :: "r"((uint32_t)(addr)), "r"((uint32_t)(cnt)) : "memory")

#define MBARRIER_EXPECT_TX(addr, bytes) \
    asm volatile("mbarrier.arrive.expect_tx.shared.b64 _, [%0], %1;" :: "r"((uint32_t)(addr)), "r"((uint32_t)(bytes)) : "memory")

#define MBARRIER_ARRIVE(addr) \
    asm volatile("mbarrier.arrive.shared.b64 _, [%0];" :: "r"((uint32_t)(addr)) : "memory")

#define MBARRIER_WAIT_PARITY(mbar_addr, parity) do {                               \
    uint32_t _m = (uint32_t)(mbar_addr); uint32_t _p = (uint32_t)(parity);         \
    uint32_t _d;                                                                    \
    asm volatile("{\n\t.reg .pred p;\n\t"                                           \
        "mbarrier.try_wait.parity.acquire.cta.shared::cta.b64 p, [%1], %2;\n\t"     \
        "selp.b32 %0, 1, 0, p;\n\t}" : "=r"(_d) : "r"(_m), "r"(_p) : "memory");     \
    if (!_d) {                                                                      \
        asm volatile("{\n\t.reg .pred P1;\n\t"                                      \
        "WL_%=:\n\t"                                                                \
        "mbarrier.try_wait.parity.acquire.cta.shared::cta.b64 P1, [%0], %1, 0x989680;\n\t" \
        "@P1 bra.uni WD_%=;\n\t"                                                    \
        "bra.uni WL_%=;\n\t"                                                        \
        "WD_%=:\n\t}" :: "r"(_m), "r"(_p) : "memory");                              \
    }                                                                               \
} while (0)

#define MBARRIER_WAIT_PARITY_RELAXED(mbar_addr, parity) do {                       \
    uint32_t _m = (uint32_t)(mbar_addr); uint32_t _p = (uint32_t)(parity);         \
    uint32_t _d;                                                                    \
    asm volatile("{\n\t.reg .pred p;\n\t"                                           \
        "mbarrier.try_wait.parity.relaxed.cta.shared::cta.b64 p, [%1], %2, 0x989680;\n\t" \
        "selp.b32 %0, 1, 0, p;\n\t}" : "=r"(_d) : "r"(_m), "r"(_p) : "memory");     \
    if (!_d) {                                                                      \
        asm volatile("{\n\t.reg .pred P1;\n\t"                                      \
        "WL_%=:\n\t"                                                                \
        "mbarrier.try_wait.parity.relaxed.cta.shared::cta.b64 P1, [%0], %1, 0x989680;\n\t" \
        "@P1 bra.uni WD_%=;\n\t"                                                    \
        "bra.uni WL_%=;\n\t"                                                        \
        "WD_%=:\n\t}" :: "r"(_m), "r"(_p) : "memory");                              \
    }                                                                               \
} while (0)

static __device__ __forceinline__ void bulk_g2s(uint32_t dst, const void* src,
                                                uint32_t bytes, uint32_t mbar) {
    asm volatile(
        "cp.async.bulk.shared::cluster.global.mbarrier::complete_tx::bytes [%0], [%1], %2, [%3];"
        :: "r"(dst), "l"(src), "r"(bytes), "r"(mbar) : "memory");
}

static __device__ __forceinline__ void ldsm4(uint32_t* r, uint32_t addr) {
    asm volatile("ldmatrix.sync.aligned.m8n8.x4.shared.b16 {%0,%1,%2,%3}, [%4];"
        : "=r"(r[0]), "=r"(r[1]), "=r"(r[2]), "=r"(r[3]) : "r"(addr));
}

static __device__ __forceinline__ void imma(int* d, const uint32_t* a,
                                            uint32_t b0, uint32_t b1) {
    asm volatile(
        "mma.sync.aligned.m16n8k32.row.col.s32.s8.s8.s32 "
        "{%0,%1,%2,%3}, {%4,%5,%6,%7}, {%8,%9}, {%0,%1,%2,%3};"
        : "+r"(d[0]), "+r"(d[1]), "+r"(d[2]), "+r"(d[3])
        : "r"(a[0]), "r"(a[1]), "r"(a[2]), "r"(a[3]), "r"(b0), "r"(b1));
}

// ---------------- geometry ----------------------------------------------------
static constexpr int      NCHUNK      = 32;       // 4096 / 128
static constexpr uint32_t TILE_BYTES  = 16384;    // 128 rows x 128 k-bytes
static constexpr int      STAGES      = 4;
static constexpr uint32_t STAGE_BYTES = 3 * TILE_BYTES;   // A0 + A1 + B = 48KB
static constexpr uint32_t OFF_FULL    = 0;        // 4 x 8B
static constexpr uint32_t OFF_EMPTY   = 64;       // 4 x 8B
static constexpr uint32_t OFF_STAGE   = 1024;
static constexpr uint32_t SMEM_DYN    = OFF_STAGE + STAGES * STAGE_BYTES;  // 197632

// ---------------- merged prologue: pack x (y=0) and sign(W) (y=1) ------------
__global__ void __launch_bounds__(256) prep_kernel(const float* __restrict__ x,
                                                   const float* __restrict__ w) {
    const int row = blockIdx.x;
    const int tid = threadIdx.x;
    const bool is_x = (blockIdx.y == 0);
    const float* src = (is_x ? x : w) + (size_t)row * 4096;

    float4 v[4];
    #pragma unroll
    for (int i = 0; i < 4; i++) v[i] = ((const float4*)src)[tid * 4 + i];

    const uint32_t inrow = (uint32_t)((tid & 7) * 16);
    const uint32_t swzc  = inrow ^ (uint32_t)((row & 7) << 4);
    const size_t off = ((size_t)(row >> 7) * 32 + (size_t)(tid >> 3)) * TILE_BYTES
                     + (size_t)((row & 127) * 128) + swzc;

    if (is_x) {
        float mx = 0.f, sm = 0.f;
        #pragma unroll
        for (int i = 0; i < 4; i++) {
            mx = fmaxf(mx, fmaxf(fmaxf(fabsf(v[i].x), fabsf(v[i].y)),
                                 fmaxf(fabsf(v[i].z), fabsf(v[i].w))));
            sm += (v[i].x + v[i].y) + (v[i].z + v[i].w);
        }
        __shared__ float smax[256], ssum[256];
        smax[tid] = mx; ssum[tid] = sm;
        __syncthreads();
        for (int s = 128; s > 0; s >>= 1) {
            if (tid < s) {
                smax[tid] = fmaxf(smax[tid], smax[tid + s]);
                ssum[tid] += ssum[tid + s];
            }
            __syncthreads();
        }
        const float maxv = smax[0];
        const float inv  = (maxv > 0.f) ? 127.f / maxv : 0.f;

        uint32_t p1[4], p2[4];
        #pragma unroll
        for (int i = 0; i < 4; i++) {
            float e[4] = {v[i].x, v[i].y, v[i].z, v[i].w};
            uint32_t w1 = 0, w2 = 0;
            #pragma unroll
            for (int b = 0; b < 4; b++) {
                float r0 = e[b] * inv;
                int q1 = __float2int_rn(r0);
                int q2 = __float2int_rn((r0 - (float)q1) * 254.f);
                w1 |= (uint32_t)(q1 & 0xff) << (8 * b);
                w2 |= (uint32_t)(q2 & 0xff) << (8 * b);
            }
            p1[i] = w1; p2[i] = w2;
        }
        *(uint4*)((char*)g_a0 + off) = make_uint4(p1[0], p1[1], p1[2], p1[3]);
        *(uint4*)((char*)g_a1 + off) = make_uint4(p2[0], p2[1], p2[2], p2[3]);
        if (tid == 0) {
            g_scale[row]  = (maxv > 0.f) ? maxv / 127.f : 0.f;
            g_rowsum[row] = ssum[0];
        }
    } else {
        uint32_t p[4];
        #pragma unroll
        for (int i = 0; i < 4; i++) {
            float e[4] = {v[i].x, v[i].y, v[i].z, v[i].w};
            uint32_t wq = 0;
            #pragma unroll
            for (int b = 0; b < 4; b++) {
                int q = (e[b] > 0.f) ? 1 : ((e[b] < 0.f) ? -1 : 0);
                wq |= (uint32_t)(q & 0xff) << (8 * b);
            }
            p[i] = wq;
        }
        *(uint4*)((char*)g_b + off) = make_uint4(p[0], p[1], p[2], p[3]);
    }
}

// ---------------- main GEMM (identical to the proven 1870us core) -------------
// grid (32 ntile, 32 mtile), 512 threads: 16 compute warps (4M x 4N, 32x32 tile).
// Producer duties inlined into warp 0 lane 0 (self-issued 4-stage pipeline).
__global__ void __launch_bounds__(512, 1)
gemm_kernel(const float* __restrict__ wscale, const float* __restrict__ wbias,
            float* __restrict__ out) {
    extern __shared__ __align__(1024) char smem[];
    const uint32_t sb = smem_u32(smem);
    const int tid = threadIdx.x;
    const int wid = tid >> 5;
    const int lane = tid & 31;
    const int ntile = blockIdx.x;
    const int mtile = blockIdx.y;

    const char* pa0 = (const char*)g_a0 + (size_t)mtile * (32u * TILE_BYTES);
    const char* pa1 = (const char*)g_a1 + (size_t)mtile * (32u * TILE_BYTES);
    const char* pb  = (const char*)g_b  + (size_t)ntile * (32u * TILE_BYTES);

    if (tid == 0) {
        #pragma unroll
        for (int s = 0; s < STAGES; s++) {
            MBARRIER_INIT(sb + OFF_FULL  + 8u * s, 1);
            MBARRIER_INIT(sb + OFF_EMPTY + 8u * s, 16);
        }
    }
    __syncthreads();

    // prime the pipeline: issue chunks 0..3
    if (tid == 0) {
        #pragma unroll
        for (int s = 0; s < STAGES; s++) {
            uint32_t fb = sb + OFF_FULL + 8u * s;
            MBARRIER_EXPECT_TX(fb, STAGE_BYTES);
            uint32_t dst = sb + OFF_STAGE + (uint32_t)s * STAGE_BYTES;
            size_t co = (size_t)s * TILE_BYTES;
            bulk_g2s(dst,                  pa0 + co, TILE_BYTES, fb);
            bulk_g2s(dst + TILE_BYTES,     pa1 + co, TILE_BYTES, fb);
            bulk_g2s(dst + 2 * TILE_BYTES, pb  + co, TILE_BYTES, fb);
        }
    }

    // ---------------- per-warp tiling: 4(M) x 4(N), warp tile 32x32 -----------
    const int mw  = wid >> 2;         // 0..3
    const int nwp = wid & 3;          // 0..3
    const int rA = lane & 15;
    const uint32_t hb = (uint32_t)((lane >> 4) * 16);
    const uint32_t ph_sw = (uint32_t)((rA & 7) << 4);

    uint32_t rowA[2], rowB[2];
    #pragma unroll
    for (int t = 0; t < 2; t++) rowA[t] = (uint32_t)((mw * 32 + t * 16 + rA) * 128);
    #pragma unroll
    for (int j = 0; j < 2; j++) rowB[j] = (uint32_t)((nwp * 32 + j * 16 + rA) * 128);
    uint32_t colx[4];
    #pragma unroll
    for (int ks = 0; ks < 4; ks++) colx[ks] = ((uint32_t)(ks * 32) + hb) ^ ph_sw;

    int acc0[2][4][4];   // [t][j*2+n8][reg]
    int acc1[2][4][4];
    #pragma unroll
    for (int t = 0; t < 2; t++)
        #pragma unroll
        for (int u = 0; u < 4; u++)
            #pragma unroll
            for (int i = 0; i < 4; i++) { acc0[t][u][i] = 0; acc1[t][u][i] = 0; }

    for (int ch = 0; ch < NCHUNK; ch++) {
        const int st = ch & 3;
        const int ph = (ch >> 2) & 1;
        MBARRIER_WAIT_PARITY(sb + OFF_FULL + 8u * st, ph);
        const uint32_t SA0 = sb + OFF_STAGE + (uint32_t)st * STAGE_BYTES;
        const uint32_t SA1 = SA0 + TILE_BYTES;
        const uint32_t SB  = SA0 + 2 * TILE_BYTES;

        #pragma unroll
        for (int ks = 0; ks < 4; ks++) {
            uint32_t a0f[2][4], a1f[2][4], bf[2][4];
            #pragma unroll
            for (int t = 0; t < 2; t++) {
                ldsm4(a0f[t], SA0 + rowA[t] + colx[ks]);
                ldsm4(a1f[t], SA1 + rowA[t] + colx[ks]);
            }
            #pragma unroll
            for (int j = 0; j < 2; j++) ldsm4(bf[j], SB + rowB[j] + colx[ks]);

            #pragma unroll
            for (int t = 0; t < 2; t++) {
                #pragma unroll
                for (int j = 0; j < 2; j++) {
                    imma(acc0[t][2 * j],     a0f[t], bf[j][0], bf[j][2]);
                    imma(acc0[t][2 * j + 1], a0f[t], bf[j][1], bf[j][3]);
                    imma(acc1[t][2 * j],     a1f[t], bf[j][0], bf[j][2]);
                    imma(acc1[t][2 * j + 1], a1f[t], bf[j][1], bf[j][3]);
                }
            }
        }
        if (lane == 0) MBARRIER_ARRIVE(sb + OFF_EMPTY + 8u * st);
        // self-issued producer: refill this stage with chunk ch+4
        if (tid == 0 && ch + STAGES < NCHUNK) {
            MBARRIER_WAIT_PARITY_RELAXED(sb + OFF_EMPTY + 8u * st, ph);
            uint32_t fb = sb + OFF_FULL + 8u * st;
            MBARRIER_EXPECT_TX(fb, STAGE_BYTES);
            uint32_t dst = sb + OFF_STAGE + (uint32_t)st * STAGE_BYTES;
            size_t co = (size_t)(ch + STAGES) * TILE_BYTES;
            bulk_g2s(dst,                  pa0 + co, TILE_BYTES, fb);
            bulk_g2s(dst + TILE_BYTES,     pa1 + co, TILE_BYTES, fb);
            bulk_g2s(dst + 2 * TILE_BYTES, pb  + co, TILE_BYTES, fb);
        }
    }

    // ---------------- epilogue ----------------
    const float inv254 = 1.f / 254.f;
    const int lg = lane >> 2;           // 0..7
    const int lc = (lane & 3) * 2;      // 0,2,4,6
    const int nbase = ntile * 128 + nwp * 32 + lc;
    #pragma unroll
    for (int t = 0; t < 2; t++) {
        #pragma unroll
        for (int half = 0; half < 2; half++) {
            const int m = mtile * 128 + mw * 32 + t * 16 + lg + half * 8;
            const float alpha = g_scale[m];
            const float rs    = g_rowsum[m];
            float* orow = out + (size_t)m * 4096;
            const int i0 = half * 2, i1 = half * 2 + 1;
            #pragma unroll
            for (int u = 0; u < 4; u++) {
                const int n = nbase + u * 8;
                float v0 = (float)acc0[t][u][i0] + (float)acc1[t][u][i0] * inv254;
                float v1 = (float)acc0[t][u][i1] + (float)acc1[t][u][i1] * inv254;
                float2 o;
                o.x = __ldg(wscale + n)     * (alpha * v0) + __ldg(wbias + n)     * rs;
                o.y = __ldg(wscale + n + 1) * (alpha * v1) + __ldg(wbias + n + 1) * rs;
                *(float2*)(orow + n) = o;
            }
        }
    }
}

// ---------------- launch --------------------------------------------------------
extern "C" void kernel_launch(void* const* d_in, const int* in_sizes, int n_in,
                              void* d_out, int out_size) {
    (void)in_sizes; (void)n_in; (void)out_size;
    const float* x      = (const float*)d_in[0];   // [2,2048,4096]
    const float* weight = (const float*)d_in[1];   // [4096,4096]
    const float* wscale = (const float*)d_in[2];   // [4096,1]
    const float* wbias  = (const float*)d_in[3];   // [4096,1]
    float* out = (float*)d_out;

    cudaFuncSetAttribute(gemm_kernel, cudaFuncAttributeMaxDynamicSharedMemorySize,
                         (int)SMEM_DYN);

    prep_kernel<<<dim3(4096, 2), 256>>>(x, weight);
    gemm_kernel<<<dim3(32, 32), 512, SMEM_DYN>>>(wscale, wbias, out);
}

// round 10
// speedup vs baseline: 1.5561x; 1.1241x over previous
#include <cuda_runtime.h>
#include <cuda_bf16.h>
#include <cstdint>

// ============================================================================
// BinaryLinearWscales (GB300). Tensor pipe (mma.sync s8) is a real but
// slow-path unit (~245 MAC/cyc/SM, measured 94.7% busy binder in R9).
// This round: split precision levels ACROSS pipes.
//   level-1 (q1):  mma.sync m16n8k32.s8  -> tensor pipe  (half prior work)
//   level-2 (q2):  dp4a                  -> fma pipe     (was 97% idle)
//   x ~= alpha_m * (q1 + q2/254), sign(W) exact in s8.
//   out[m,n] = wscale[n]*alpha_m*(S1 + S2/254) + wbias[n]*rowsum[m]
// CTA 256 thr, tile 128Mx64N, 4-stage mbarrier pipeline (proven R9 skeleton).
// ============================================================================

// ---------------- device scratch (pre-swizzled tiled s8) --------------------
// Layout: [tile(128 rows)][kchunk(128 bytes)] -> 16KB tile, SW128 swizzled.
__device__ __align__(16384) int8_t g_a0[16777216];   // 16 MB: q1 of x
__device__ __align__(16384) int8_t g_a1[16777216];   // 16 MB: q2 of x
__device__ __align__(16384) int8_t g_b [16777216];   // 16 MB: sign(W)
__device__ float g_scale [4096];
__device__ float g_rowsum[4096];

// ---------------- PTX helpers ------------------------------------------------
static __device__ __forceinline__ uint32_t smem_u32(const void* p) {
    uint32_t a;
    asm("{ .reg .u64 t; cvta.to.shared.u64 t, %1; cvt.u32.u64 %0, t; }" : "=r"(a) : "l"(p));
    return a;
}

#define MBARRIER_INIT(addr, cnt) \
    asm volatile("mbarrier.init.shared.b64 [%0], %1;" :: "r"((uint32_t)(addr)), "r"((uint32_t)(cnt)) : "memory")

#define MBARRIER_EXPECT_TX(addr, bytes) \
    asm volatile("mbarrier.arrive.expect_tx.shared.b64 _, [%0], %1;" :: "r"((uint32_t)(addr)), "r"((uint32_t)(bytes)) : "memory")

#define MBARRIER_ARRIVE(addr) \
    asm volatile("mbarrier.arrive.shared.b64 _, [%0];" :: "r"((uint32_t)(addr)) : "memory")

#define MBARRIER_WAIT_PARITY(mbar_addr, parity) do {                               \
    uint32_t _m = (uint32_t)(mbar_addr); uint32_t _p = (uint32_t)(parity);         \
    uint32_t _d;                                                                    \
    asm volatile("{\n\t.reg .pred p;\n\t"                                           \
        "mbarrier.try_wait.parity.acquire.cta.shared::cta.b64 p, [%1], %2;\n\t"     \
        "selp.b32 %0, 1, 0, p;\n\t}" : "=r"(_d) : "r"(_m), "r"(_p) : "memory");     \
    if (!_d) {                                                                      \
        asm volatile("{\n\t.reg .pred P1;\n\t"                                      \
        "WL_%=:\n\t"                                                                \
        "mbarrier.try_wait.parity.acquire.cta.shared::cta.b64 P1, [%0], %1, 0x989680;\n\t" \
        "@P1 bra.uni WD_%=;\n\t"                                                    \
        "bra.uni WL_%=;\n\t"                                                        \
        "WD_%=:\n\t}" :: "r"(_m), "r"(_p) : "memory");                              \
    }                                                                               \
} while (0)

#define MBARRIER_WAIT_PARITY_RELAXED(mbar_addr, parity) do {                       \
    uint32_t _m = (uint32_t)(mbar_addr); uint32_t _p = (uint32_t)(parity);         \
    uint32_t _d;                                                                    \
    asm volatile("{\n\t.reg .pred p;\n\t"                                           \
        "mbarrier.try_wait.parity.relaxed.cta.shared::cta.b64 p, [%1], %2, 0x989680;\n\t" \
        "selp.b32 %0, 1, 0, p;\n\t}" : "=r"(_d) : "r"(_m), "r"(_p) : "memory");     \
    if (!_d) {                                                                      \
        asm volatile("{\n\t.reg .pred P1;\n\t"                                      \
        "WL_%=:\n\t"                                                                \
        "mbarrier.try_wait.parity.relaxed.cta.shared::cta.b64 P1, [%0], %1, 0x989680;\n\t" \
        "@P1 bra.uni WD_%=;\n\t"                                                    \
        "bra.uni WL_%=;\n\t"                                                        \
        "WD_%=:\n\t}" :: "r"(_m), "r"(_p) : "memory");                              \
    }                                                                               \
} while (0)

static __device__ __forceinline__ void bulk_g2s(uint32_t dst, const void* src,
                                                uint32_t bytes, uint32_t mbar) {
    asm volatile(
        "cp.async.bulk.shared::cluster.global.mbarrier::complete_tx::bytes [%0], [%1], %2, [%3];"
        :: "r"(dst), "l"(src), "r"(bytes), "r"(mbar) : "memory");
}

static __device__ __forceinline__ void ldsm4(uint32_t* r, uint32_t addr) {
    asm volatile("ldmatrix.sync.aligned.m8n8.x4.shared.b16 {%0,%1,%2,%3}, [%4];"
        : "=r"(r[0]), "=r"(r[1]), "=r"(r[2]), "=r"(r[3]) : "r"(addr));
}

static __device__ __forceinline__ void imma(int* d, const uint32_t* a,
                                            uint32_t b0, uint32_t b1) {
    asm volatile(
        "mma.sync.aligned.m16n8k32.row.col.s32.s8.s8.s32 "
        "{%0,%1,%2,%3}, {%4,%5,%6,%7}, {%8,%9}, {%0,%1,%2,%3};"
        : "+r"(d[0]), "+r"(d[1]), "+r"(d[2]), "+r"(d[3])
        : "r"(a[0]), "r"(a[1]), "r"(a[2]), "r"(a[3]), "r"(b0), "r"(b1));
}

// ---------------- geometry ----------------------------------------------------
static constexpr int      NCHUNK      = 32;       // 4096 / 128
static constexpr uint32_t TILE_BYTES  = 16384;    // 128 rows x 128 k-bytes
static constexpr uint32_t BTILE_BYTES = 8192;     // 64 rows x 128 k-bytes
static constexpr int      STAGES      = 4;
static constexpr uint32_t OFF_A1      = 16384;
static constexpr uint32_t OFF_B       = 32768;
static constexpr uint32_t STAGE_BYTES = 40960;    // A0 16K + A1 16K + B 8K
static constexpr uint32_t OFF_FULL    = 0;
static constexpr uint32_t OFF_EMPTY   = 64;
static constexpr uint32_t OFF_STAGE   = 1024;
static constexpr uint32_t SMEM_DYN    = OFF_STAGE + STAGES * STAGE_BYTES;  // 164864

// ---------------- merged prologue: pack x (y=0) and sign(W) (y=1) ------------
__global__ void __launch_bounds__(256) prep_kernel(const float* __restrict__ x,
                                                   const float* __restrict__ w) {
    const int row = blockIdx.x;
    const int tid = threadIdx.x;
    const bool is_x = (blockIdx.y == 0);
    const float* src = (is_x ? x : w) + (size_t)row * 4096;

    float4 v[4];
    #pragma unroll
    for (int i = 0; i < 4; i++) v[i] = ((const float4*)src)[tid * 4 + i];

    const uint32_t inrow = (uint32_t)((tid & 7) * 16);
    const uint32_t swzc  = inrow ^ (uint32_t)((row & 7) << 4);
    const size_t off = ((size_t)(row >> 7) * 32 + (size_t)(tid >> 3)) * TILE_BYTES
                     + (size_t)((row & 127) * 128) + swzc;

    if (is_x) {
        float mx = 0.f, sm = 0.f;
        #pragma unroll
        for (int i = 0; i < 4; i++) {
            mx = fmaxf(mx, fmaxf(fmaxf(fabsf(v[i].x), fabsf(v[i].y)),
                                 fmaxf(fabsf(v[i].z), fabsf(v[i].w))));
            sm += (v[i].x + v[i].y) + (v[i].z + v[i].w);
        }
        __shared__ float smax[256], ssum[256];
        smax[tid] = mx; ssum[tid] = sm;
        __syncthreads();
        for (int s = 128; s > 0; s >>= 1) {
            if (tid < s) {
                smax[tid] = fmaxf(smax[tid], smax[tid + s]);
                ssum[tid] += ssum[tid + s];
            }
            __syncthreads();
        }
        const float maxv = smax[0];
        const float inv  = (maxv > 0.f) ? 127.f / maxv : 0.f;

        uint32_t p1[4], p2[4];
        #pragma unroll
        for (int i = 0; i < 4; i++) {
            float e[4] = {v[i].x, v[i].y, v[i].z, v[i].w};
            uint32_t w1 = 0, w2 = 0;
            #pragma unroll
            for (int b = 0; b < 4; b++) {
                float r0 = e[b] * inv;
                int q1 = __float2int_rn(r0);
                int q2 = __float2int_rn((r0 - (float)q1) * 254.f);
                w1 |= (uint32_t)(q1 & 0xff) << (8 * b);
                w2 |= (uint32_t)(q2 & 0xff) << (8 * b);
            }
            p1[i] = w1; p2[i] = w2;
        }
        *(uint4*)((char*)g_a0 + off) = make_uint4(p1[0], p1[1], p1[2], p1[3]);
        *(uint4*)((char*)g_a1 + off) = make_uint4(p2[0], p2[1], p2[2], p2[3]);
        if (tid == 0) {
            g_scale[row]  = (maxv > 0.f) ? maxv / 127.f : 0.f;
            g_rowsum[row] = ssum[0];
        }
    } else {
        uint32_t p[4];
        #pragma unroll
        for (int i = 0; i < 4; i++) {
            float e[4] = {v[i].x, v[i].y, v[i].z, v[i].w};
            uint32_t wq = 0;
            #pragma unroll
            for (int b = 0; b < 4; b++) {
                int q = (e[b] > 0.f) ? 1 : ((e[b] < 0.f) ? -1 : 0);
                wq |= (uint32_t)(q & 0xff) << (8 * b);
            }
            p[i] = wq;
        }
        *(uint4*)((char*)g_b + off) = make_uint4(p[0], p[1], p[2], p[3]);
    }
}

// ---------------- main GEMM ----------------------------------------------------
// grid (64 ntile, 32 mtile), 256 threads. CTA tile 128M x 64N.
// 8 warps: mma level-1 tiling 4Mx2N (32x32), dp4a level-2 per-thread 8x4.
__global__ void __launch_bounds__(256, 1)
gemm_kernel(const float* __restrict__ wscale, const float* __restrict__ wbias,
            float* __restrict__ out) {
    extern __shared__ __align__(1024) char smem[];
    const uint32_t sb = smem_u32(smem);
    const int tid = threadIdx.x;
    const int wid = tid >> 5;
    const int lane = tid & 31;
    const int ntile = blockIdx.x;   // 0..63
    const int mtile = blockIdx.y;   // 0..31

    const char* pa0 = (const char*)g_a0 + (size_t)mtile * (32u * TILE_BYTES);
    const char* pa1 = (const char*)g_a1 + (size_t)mtile * (32u * TILE_BYTES);
    const char* pb  = (const char*)g_b  + (size_t)(ntile >> 1) * (32u * TILE_BYTES)
                    + (size_t)(ntile & 1) * BTILE_BYTES;

    if (tid == 0) {
        #pragma unroll
        for (int s = 0; s < STAGES; s++) {
            MBARRIER_INIT(sb + OFF_FULL  + 8u * s, 1);
            MBARRIER_INIT(sb + OFF_EMPTY + 8u * s, 8);
        }
    }
    __syncthreads();

    if (tid == 0) {
        #pragma unroll
        for (int s = 0; s < STAGES; s++) {
            uint32_t fb = sb + OFF_FULL + 8u * s;
            MBARRIER_EXPECT_TX(fb, STAGE_BYTES);
            uint32_t dst = sb + OFF_STAGE + (uint32_t)s * STAGE_BYTES;
            size_t co = (size_t)s * TILE_BYTES;
            bulk_g2s(dst,          pa0 + co, TILE_BYTES,  fb);
            bulk_g2s(dst + OFF_A1, pa1 + co, TILE_BYTES,  fb);
            bulk_g2s(dst + OFF_B,  pb  + co, BTILE_BYTES, fb);
        }
    }

    // ---- mma (level-1) tiling: 4(M) x 2(N) warps, warp tile 32x32 ----
    const int mw = wid >> 1;          // 0..3
    const int nw = wid & 1;           // 0..1
    const int rA = lane & 15;
    const uint32_t hb = (uint32_t)((lane >> 4) * 16);
    const uint32_t ph_sw = (uint32_t)((rA & 7) << 4);

    uint32_t rowA[2], rowB[2];
    #pragma unroll
    for (int t = 0; t < 2; t++) rowA[t] = (uint32_t)((mw * 32 + t * 16 + rA) * 128);
    #pragma unroll
    for (int j = 0; j < 2; j++) rowB[j] = (uint32_t)((nw * 32 + j * 16 + rA) * 128);
    uint32_t colx[4];
    #pragma unroll
    for (int ks = 0; ks < 4; ks++) colx[ks] = ((uint32_t)(ks * 32) + hb) ^ ph_sw;

    // ---- dp4a (level-2) tiling: thread -> rows {g+16i}, cols {h+16j} ----
    const int g = tid & 15;           // 0..15
    const int h = tid >> 4;           // 0..15
    const uint32_t aswz = (uint32_t)((g & 7) * 16);
    const uint32_t bswz = (uint32_t)((h & 7) * 16);

    int acc0[2][4][4];                // level-1 mma accumulators
    int accL[8][4];                   // level-2 dp4a accumulators
    #pragma unroll
    for (int t = 0; t < 2; t++)
        #pragma unroll
        for (int u = 0; u < 4; u++)
            #pragma unroll
            for (int i = 0; i < 4; i++) acc0[t][u][i] = 0;
    #pragma unroll
    for (int i = 0; i < 8; i++)
        #pragma unroll
        for (int j = 0; j < 4; j++) accL[i][j] = 0;

    for (int ch = 0; ch < NCHUNK; ch++) {
        const int st = ch & 3;
        const int ph = (ch >> 2) & 1;
        MBARRIER_WAIT_PARITY(sb + OFF_FULL + 8u * st, ph);
        const uint32_t SA0 = sb + OFF_STAGE + (uint32_t)st * STAGE_BYTES;
        const uint32_t SA1 = SA0 + OFF_A1;
        const uint32_t SB  = SA0 + OFF_B;
        const char* cSA1 = smem + OFF_STAGE + (uint32_t)st * STAGE_BYTES + OFF_A1;
        const char* cSB  = smem + OFF_STAGE + (uint32_t)st * STAGE_BYTES + OFF_B;

        #pragma unroll
        for (int ks = 0; ks < 4; ks++) {
            // ---- tensor pipe: level-1 mma (8 imma) ----
            uint32_t a0f[2][4], bf[2][4];
            #pragma unroll
            for (int t = 0; t < 2; t++) ldsm4(a0f[t], SA0 + rowA[t] + colx[ks]);
            #pragma unroll
            for (int j = 0; j < 2; j++) ldsm4(bf[j], SB + rowB[j] + colx[ks]);
            #pragma unroll
            for (int t = 0; t < 2; t++) {
                #pragma unroll
                for (int j = 0; j < 2; j++) {
                    imma(acc0[t][2 * j],     a0f[t], bf[j][0], bf[j][2]);
                    imma(acc0[t][2 * j + 1], a0f[t], bf[j][1], bf[j][3]);
                }
            }

            // ---- fma pipe: level-2 dp4a (2 x 16B subcolumns) ----
            #pragma unroll
            for (int sub = 0; sub < 2; sub++) {
                const uint32_t col = (uint32_t)(ks * 32 + sub * 16);
                int4 a4[8], b4[4];
                #pragma unroll
                for (int i = 0; i < 8; i++)
                    a4[i] = *(const int4*)(cSA1 + (g + 16 * i) * 128 + (col ^ aswz));
                #pragma unroll
                for (int j = 0; j < 4; j++)
                    b4[j] = *(const int4*)(cSB + (h + 16 * j) * 128 + (col ^ bswz));
                #pragma unroll
                for (int i = 0; i < 8; i++)
                    #pragma unroll
                    for (int j = 0; j < 4; j++) {
                        int* a = &accL[i][j];
                        *a = __dp4a(a4[i].x, b4[j].x, *a);
                        *a = __dp4a(a4[i].y, b4[j].y, *a);
                        *a = __dp4a(a4[i].z, b4[j].z, *a);
                        *a = __dp4a(a4[i].w, b4[j].w, *a);
                    }
            }
        }
        if (lane == 0) MBARRIER_ARRIVE(sb + OFF_EMPTY + 8u * st);
        if (tid == 0 && ch + STAGES < NCHUNK) {
            MBARRIER_WAIT_PARITY_RELAXED(sb + OFF_EMPTY + 8u * st, ph);
            uint32_t fb = sb + OFF_FULL + 8u * st;
            MBARRIER_EXPECT_TX(fb, STAGE_BYTES);
            uint32_t dst = sb + OFF_STAGE + (uint32_t)st * STAGE_BYTES;
            size_t co = (size_t)(ch + STAGES) * TILE_BYTES;
            bulk_g2s(dst,          pa0 + co, TILE_BYTES,  fb);
            bulk_g2s(dst + OFF_A1, pa1 + co, TILE_BYTES,  fb);
            bulk_g2s(dst + OFF_B,  pb  + co, BTILE_BYTES, fb);
        }
    }

    // ---------------- epilogue: stage level-2 via SMEM, combine in mma layout --
    __syncthreads();                       // all warps done with stage buffers
    int* sInt = (int*)smem;                // 128 x 68 ints = 34816 B
    #pragma unroll
    for (int i = 0; i < 8; i++)
        #pragma unroll
        for (int j = 0; j < 4; j++)
            sInt[(g + 16 * i) * 68 + (h + 16 * j)] = accL[i][j];
    __syncthreads();

    const float inv254 = 1.f / 254.f;
    const int lg = lane >> 2;           // 0..7
    const int lc = (lane & 3) * 2;      // 0,2,4,6
    const int nlb = nw * 32 + lc;       // local n base
    #pragma unroll
    for (int t = 0; t < 2; t++) {
        #pragma unroll
        for (int half = 0; half < 2; half++) {
            const int ml = mw * 32 + t * 16 + lg + half * 8;   // local m
            const int m  = mtile * 128 + ml;
            const float alpha = g_scale[m];
            const float rs    = g_rowsum[m];
            float* orow = out + (size_t)m * 4096;
            const int i0 = half * 2, i1 = half * 2 + 1;
            #pragma unroll
            for (int u = 0; u < 4; u++) {
                const int nl = nlb + u * 8;
                const int n  = ntile * 64 + nl;
                float v0 = (float)acc0[t][u][i0] + (float)sInt[ml * 68 + nl]     * inv254;
                float v1 = (float)acc0[t][u][i1] + (float)sInt[ml * 68 + nl + 1] * inv254;
                float2 o;
                o.x = __ldg(wscale + n)     * (alpha * v0) + __ldg(wbias + n)     * rs;
                o.y = __ldg(wscale + n + 1) * (alpha * v1) + __ldg(wbias + n + 1) * rs;
                *(float2*)(orow + n) = o;
            }
        }
    }
}

// ---------------- launch --------------------------------------------------------
extern "C" void kernel_launch(void* const* d_in, const int* in_sizes, int n_in,
                              void* d_out, int out_size) {
    (void)in_sizes; (void)n_in; (void)out_size;
    const float* x      = (const float*)d_in[0];   // [2,2048,4096]
    const float* weight = (const float*)d_in[1];   // [4096,4096]
    const float* wscale = (const float*)d_in[2];   // [4096,1]
    const float* wbias  = (const float*)d_in[3];   // [4096,1]
    float* out = (float*)d_out;

    cudaFuncSetAttribute(gemm_kernel, cudaFuncAttributeMaxDynamicSharedMemorySize,
                         (int)SMEM_DYN);

    prep_kernel<<<dim3(4096, 2), 256>>>(x, weight);
    gemm_kernel<<<dim3(64, 32), 256, SMEM_DYN>>>(wscale, wbias, out);
}

// round 11
// speedup vs baseline: 1.7958x; 1.1540x over previous
#include <cuda_runtime.h>
#include <cuda_bf16.h>
#include <cstdint>

// ============================================================================
// BinaryLinearWscales (GB300). Hybrid dual-pipe GEMM:
//   level-1 (q1):  mma.sync m16n8k32.s8 -> tensor pipe (half work, ~880us busy)
//   level-2 (q2):  dp4a                 -> fma pipe (full-rate, ~440us busy)
//   x ~= alpha_m * (q1 + q2/254), sign(W) exact in s8.
// R11: 512 thr/CTA (16 warps/SM, 4/SMSP) to fix issue starvation (R10 occ=12.5%).
// Per-warp work halved; registers ~120 -> no spills at the 128-reg budget.
// ============================================================================

// ---------------- device scratch (pre-swizzled tiled s8) --------------------
__device__ __align__(16384) int8_t g_a0[16777216];   // 16 MB: q1 of x
__device__ __align__(16384) int8_t g_a1[16777216];   // 16 MB: q2 of x
__device__ __align__(16384) int8_t g_b [16777216];   // 16 MB: sign(W)
__device__ float g_scale [4096];
__device__ float g_rowsum[4096];

// ---------------- PTX helpers ------------------------------------------------
static __device__ __forceinline__ uint32_t smem_u32(const void* p) {
    uint32_t a;
    asm("{ .reg .u64 t; cvta.to.shared.u64 t, %1; cvt.u32.u64 %0, t; }" : "=r"(a) : "l"(p));
    return a;
}

#define MBARRIER_INIT(addr, cnt) \
    asm volatile("mbarrier.init.shared.b64 [%0], %1;" :: "r"((uint32_t)(addr)), "r"((uint32_t)(cnt)) : "memory")

#define MBARRIER_EXPECT_TX(addr, bytes) \
    asm volatile("mbarrier.arrive.expect_tx.shared.b64 _, [%0], %1;" :: "r"((uint32_t)(addr)), "r"((uint32_t)(bytes)) : "memory")

#define MBARRIER_ARRIVE(addr) \
    asm volatile("mbarrier.arrive.shared.b64 _, [%0];" :: "r"((uint32_t)(addr)) : "memory")

#define MBARRIER_WAIT_PARITY(mbar_addr, parity) do {                               \
    uint32_t _m = (uint32_t)(mbar_addr); uint32_t _p = (uint32_t)(parity);         \
    uint32_t _d;                                                                    \
    asm volatile("{\n\t.reg .pred p;\n\t"                                           \
        "mbarrier.try_wait.parity.acquire.cta.shared::cta.b64 p, [%1], %2;\n\t"     \
        "selp.b32 %0, 1, 0, p;\n\t}" : "=r"(_d) : "r"(_m), "r"(_p) : "memory");     \
    if (!_d) {                                                                      \
        asm volatile("{\n\t.reg .pred P1;\n\t"                                      \
        "WL_%=:\n\t"                                                                \
        "mbarrier.try_wait.parity.acquire.cta.shared::cta.b64 P1, [%0], %1, 0x989680;\n\t" \
        "@P1 bra.uni WD_%=;\n\t"                                                    \
        "bra.uni WL_%=;\n\t"                                                        \
        "WD_%=:\n\t}" :: "r"(_m), "r"(_p) : "memory");                              \
    }                                                                               \
} while (0)

#define MBARRIER_WAIT_PARITY_RELAXED(mbar_addr, parity) do {                       \
    uint32_t _m = (uint32_t)(mbar_addr); uint32_t _p = (uint32_t)(parity);         \
    uint32_t _d;                                                                    \
    asm volatile("{\n\t.reg .pred p;\n\t"                                           \
        "mbarrier.try_wait.parity.relaxed.cta.shared::cta.b64 p, [%1], %2, 0x989680;\n\t" \
        "selp.b32 %0, 1, 0, p;\n\t}" : "=r"(_d) : "r"(_m), "r"(_p) : "memory");     \
    if (!_d) {                                                                      \
        asm volatile("{\n\t.reg .pred P1;\n\t"                                      \
        "WL_%=:\n\t"                                                                \
        "mbarrier.try_wait.parity.relaxed.cta.shared::cta.b64 P1, [%0], %1, 0x989680;\n\t" \
        "@P1 bra.uni WD_%=;\n\t"                                                    \
        "bra.uni WL_%=;\n\t"                                                        \
        "WD_%=:\n\t}" :: "r"(_m), "r"(_p) : "memory");                              \
    }                                                                               \
} while (0)

static __device__ __forceinline__ void bulk_g2s(uint32_t dst, const void* src,
                                                uint32_t bytes, uint32_t mbar) {
    asm volatile(
        "cp.async.bulk.shared::cluster.global.mbarrier::complete_tx::bytes [%0], [%1], %2, [%3];"
        :: "r"(dst), "l"(src), "r"(bytes), "r"(mbar) : "memory");
}

static __device__ __forceinline__ void ldsm4(uint32_t* r, uint32_t addr) {
    asm volatile("ldmatrix.sync.aligned.m8n8.x4.shared.b16 {%0,%1,%2,%3}, [%4];"
        : "=r"(r[0]), "=r"(r[1]), "=r"(r[2]), "=r"(r[3]) : "r"(addr));
}

static __device__ __forceinline__ void imma(int* d, const uint32_t* a,
                                            uint32_t b0, uint32_t b1) {
    asm volatile(
        "mma.sync.aligned.m16n8k32.row.col.s32.s8.s8.s32 "
        "{%0,%1,%2,%3}, {%4,%5,%6,%7}, {%8,%9}, {%0,%1,%2,%3};"
        : "+r"(d[0]), "+r"(d[1]), "+r"(d[2]), "+r"(d[3])
        : "r"(a[0]), "r"(a[1]), "r"(a[2]), "r"(a[3]), "r"(b0), "r"(b1));
}

// ---------------- geometry ----------------------------------------------------
static constexpr int      NCHUNK      = 32;       // 4096 / 128
static constexpr uint32_t TILE_BYTES  = 16384;    // 128 rows x 128 k-bytes
static constexpr uint32_t BTILE_BYTES = 8192;     // 64 rows x 128 k-bytes
static constexpr int      STAGES      = 4;
static constexpr uint32_t OFF_A1      = 16384;
static constexpr uint32_t OFF_B       = 32768;
static constexpr uint32_t STAGE_BYTES = 40960;    // A0 16K + A1 16K + B 8K
static constexpr uint32_t OFF_FULL    = 0;
static constexpr uint32_t OFF_EMPTY   = 64;
static constexpr uint32_t OFF_STAGE   = 1024;
static constexpr uint32_t SMEM_DYN    = OFF_STAGE + STAGES * STAGE_BYTES;  // 164864

// ---------------- merged prologue: pack x (y=0) and sign(W) (y=1) ------------
__global__ void __launch_bounds__(256) prep_kernel(const float* __restrict__ x,
                                                   const float* __restrict__ w) {
    const int row = blockIdx.x;
    const int tid = threadIdx.x;
    const bool is_x = (blockIdx.y == 0);
    const float* src = (is_x ? x : w) + (size_t)row * 4096;

    float4 v[4];
    #pragma unroll
    for (int i = 0; i < 4; i++) v[i] = ((const float4*)src)[tid * 4 + i];

    const uint32_t inrow = (uint32_t)((tid & 7) * 16);
    const uint32_t swzc  = inrow ^ (uint32_t)((row & 7) << 4);
    const size_t off = ((size_t)(row >> 7) * 32 + (size_t)(tid >> 3)) * TILE_BYTES
                     + (size_t)((row & 127) * 128) + swzc;

    if (is_x) {
        float mx = 0.f, sm = 0.f;
        #pragma unroll
        for (int i = 0; i < 4; i++) {
            mx = fmaxf(mx, fmaxf(fmaxf(fabsf(v[i].x), fabsf(v[i].y)),
                                 fmaxf(fabsf(v[i].z), fabsf(v[i].w))));
            sm += (v[i].x + v[i].y) + (v[i].z + v[i].w);
        }
        __shared__ float smax[256], ssum[256];
        smax[tid] = mx; ssum[tid] = sm;
        __syncthreads();
        for (int s = 128; s > 0; s >>= 1) {
            if (tid < s) {
                smax[tid] = fmaxf(smax[tid], smax[tid + s]);
                ssum[tid] += ssum[tid + s];
            }
            __syncthreads();
        }
        const float maxv = smax[0];
        const float inv  = (maxv > 0.f) ? 127.f / maxv : 0.f;

        uint32_t p1[4], p2[4];
        #pragma unroll
        for (int i = 0; i < 4; i++) {
            float e[4] = {v[i].x, v[i].y, v[i].z, v[i].w};
            uint32_t w1 = 0, w2 = 0;
            #pragma unroll
            for (int b = 0; b < 4; b++) {
                float r0 = e[b] * inv;
                int q1 = __float2int_rn(r0);
                int q2 = __float2int_rn((r0 - (float)q1) * 254.f);
                w1 |= (uint32_t)(q1 & 0xff) << (8 * b);
                w2 |= (uint32_t)(q2 & 0xff) << (8 * b);
            }
            p1[i] = w1; p2[i] = w2;
        }
        *(uint4*)((char*)g_a0 + off) = make_uint4(p1[0], p1[1], p1[2], p1[3]);
        *(uint4*)((char*)g_a1 + off) = make_uint4(p2[0], p2[1], p2[2], p2[3]);
        if (tid == 0) {
            g_scale[row]  = (maxv > 0.f) ? maxv / 127.f : 0.f;
            g_rowsum[row] = ssum[0];
        }
    } else {
        uint32_t p[4];
        #pragma unroll
        for (int i = 0; i < 4; i++) {
            float e[4] = {v[i].x, v[i].y, v[i].z, v[i].w};
            uint32_t wq = 0;
            #pragma unroll
            for (int b = 0; b < 4; b++) {
                int q = (e[b] > 0.f) ? 1 : ((e[b] < 0.f) ? -1 : 0);
                wq |= (uint32_t)(q & 0xff) << (8 * b);
            }
            p[i] = wq;
        }
        *(uint4*)((char*)g_b + off) = make_uint4(p[0], p[1], p[2], p[3]);
    }
}

// ---------------- main GEMM ----------------------------------------------------
// grid (64 ntile, 32 mtile), 512 threads. CTA tile 128M x 64N.
// 16 warps: mma 4Mx4N (warp tile 32x16); dp4a per-thread 4x4.
__global__ void __launch_bounds__(512, 1)
gemm_kernel(const float* __restrict__ wscale, const float* __restrict__ wbias,
            float* __restrict__ out) {
    extern __shared__ __align__(1024) char smem[];
    const uint32_t sb = smem_u32(smem);
    const int tid = threadIdx.x;
    const int wid = tid >> 5;
    const int lane = tid & 31;
    const int ntile = blockIdx.x;   // 0..63
    const int mtile = blockIdx.y;   // 0..31

    const char* pa0 = (const char*)g_a0 + (size_t)mtile * (32u * TILE_BYTES);
    const char* pa1 = (const char*)g_a1 + (size_t)mtile * (32u * TILE_BYTES);
    const char* pb  = (const char*)g_b  + (size_t)(ntile >> 1) * (32u * TILE_BYTES)
                    + (size_t)(ntile & 1) * BTILE_BYTES;

    if (tid == 0) {
        #pragma unroll
        for (int s = 0; s < STAGES; s++) {
            MBARRIER_INIT(sb + OFF_FULL  + 8u * s, 1);
            MBARRIER_INIT(sb + OFF_EMPTY + 8u * s, 16);
        }
    }
    __syncthreads();

    if (tid == 0) {
        #pragma unroll
        for (int s = 0; s < STAGES; s++) {
            uint32_t fb = sb + OFF_FULL + 8u * s;
            MBARRIER_EXPECT_TX(fb, STAGE_BYTES);
            uint32_t dst = sb + OFF_STAGE + (uint32_t)s * STAGE_BYTES;
            size_t co = (size_t)s * TILE_BYTES;
            bulk_g2s(dst,          pa0 + co, TILE_BYTES,  fb);
            bulk_g2s(dst + OFF_A1, pa1 + co, TILE_BYTES,  fb);
            bulk_g2s(dst + OFF_B,  pb  + co, BTILE_BYTES, fb);
        }
    }

    // ---- mma (level-1) tiling: 4(M) x 4(N) warps, warp tile 32x16 ----
    const int mw = wid >> 2;          // 0..3
    const int nw = wid & 3;           // 0..3
    const int rA = lane & 15;
    const uint32_t hb = (uint32_t)((lane >> 4) * 16);
    const uint32_t ph_sw = (uint32_t)((rA & 7) << 4);

    uint32_t rowA[2];
    #pragma unroll
    for (int t = 0; t < 2; t++) rowA[t] = (uint32_t)((mw * 32 + t * 16 + rA) * 128);
    const uint32_t rowB = (uint32_t)((nw * 16 + rA) * 128);
    uint32_t colx[4];
    #pragma unroll
    for (int ks = 0; ks < 4; ks++) colx[ks] = ((uint32_t)(ks * 32) + hb) ^ ph_sw;

    // ---- dp4a (level-2) tiling: thread -> rows {g+32i}, cols {h+16j} ----
    const int g = tid & 31;           // 0..31
    const int h = tid >> 5;           // 0..15
    const uint32_t aswz = (uint32_t)((g & 7) * 16);
    const uint32_t bswz = (uint32_t)((h & 7) * 16);

    int acc0[2][2][4];                // level-1 mma accumulators (16 regs)
    int accL[4][4];                   // level-2 dp4a accumulators (16 regs)
    #pragma unroll
    for (int t = 0; t < 2; t++)
        #pragma unroll
        for (int u = 0; u < 2; u++)
            #pragma unroll
            for (int i = 0; i < 4; i++) acc0[t][u][i] = 0;
    #pragma unroll
    for (int i = 0; i < 4; i++)
        #pragma unroll
        for (int j = 0; j < 4; j++) accL[i][j] = 0;

    for (int ch = 0; ch < NCHUNK; ch++) {
        const int st = ch & 3;
        const int ph = (ch >> 2) & 1;
        MBARRIER_WAIT_PARITY(sb + OFF_FULL + 8u * st, ph);
        const uint32_t SA0 = sb + OFF_STAGE + (uint32_t)st * STAGE_BYTES;
        const uint32_t SB  = SA0 + OFF_B;
        const char* cSA1 = smem + OFF_STAGE + (uint32_t)st * STAGE_BYTES + OFF_A1;
        const char* cSB  = smem + OFF_STAGE + (uint32_t)st * STAGE_BYTES + OFF_B;

        #pragma unroll
        for (int ks = 0; ks < 4; ks++) {
            // ---- tensor pipe: level-1 mma (4 imma) ----
            uint32_t a0f[2][4], bf[4];
            #pragma unroll
            for (int t = 0; t < 2; t++) ldsm4(a0f[t], SA0 + rowA[t] + colx[ks]);
            ldsm4(bf, SB + rowB + colx[ks]);
            #pragma unroll
            for (int t = 0; t < 2; t++) {
                imma(acc0[t][0], a0f[t], bf[0], bf[2]);
                imma(acc0[t][1], a0f[t], bf[1], bf[3]);
            }

            // ---- fma pipe: level-2 dp4a (2 x 16B subcolumns) ----
            #pragma unroll
            for (int sub = 0; sub < 2; sub++) {
                const uint32_t col = (uint32_t)(ks * 32 + sub * 16);
                int4 a4[4], b4[4];
                #pragma unroll
                for (int i = 0; i < 4; i++)
                    a4[i] = *(const int4*)(cSA1 + (g + 32 * i) * 128 + (col ^ aswz));
                #pragma unroll
                for (int j = 0; j < 4; j++)
                    b4[j] = *(const int4*)(cSB + (h + 16 * j) * 128 + (col ^ bswz));
                #pragma unroll
                for (int i = 0; i < 4; i++)
                    #pragma unroll
                    for (int j = 0; j < 4; j++) {
                        int* a = &accL[i][j];
                        *a = __dp4a(a4[i].x, b4[j].x, *a);
                        *a = __dp4a(a4[i].y, b4[j].y, *a);
                        *a = __dp4a(a4[i].z, b4[j].z, *a);
                        *a = __dp4a(a4[i].w, b4[j].w, *a);
                    }
            }
        }
        if (lane == 0) MBARRIER_ARRIVE(sb + OFF_EMPTY + 8u * st);
        if (tid == 0 && ch + STAGES < NCHUNK) {
            MBARRIER_WAIT_PARITY_RELAXED(sb + OFF_EMPTY + 8u * st, ph);
            uint32_t fb = sb + OFF_FULL + 8u * st;
            MBARRIER_EXPECT_TX(fb, STAGE_BYTES);
            uint32_t dst = sb + OFF_STAGE + (uint32_t)st * STAGE_BYTES;
            size_t co = (size_t)(ch + STAGES) * TILE_BYTES;
            bulk_g2s(dst,          pa0 + co, TILE_BYTES,  fb);
            bulk_g2s(dst + OFF_A1, pa1 + co, TILE_BYTES,  fb);
            bulk_g2s(dst + OFF_B,  pb  + co, BTILE_BYTES, fb);
        }
    }

    // ---------------- epilogue: stage level-2 via SMEM, combine in mma layout --
    __syncthreads();                       // all warps done with stage buffers
    int* sInt = (int*)smem;                // 128 x 68 ints = 34816 B
    #pragma unroll
    for (int i = 0; i < 4; i++)
        #pragma unroll
        for (int j = 0; j < 4; j++)
            sInt[(g + 32 * i) * 68 + (h + 16 * j)] = accL[i][j];
    __syncthreads();

    const float inv254 = 1.f / 254.f;
    const int lg = lane >> 2;           // 0..7
    const int lc = (lane & 3) * 2;      // 0,2,4,6
    const int nlb = nw * 16 + lc;       // local n base
    #pragma unroll
    for (int t = 0; t < 2; t++) {
        #pragma unroll
        for (int half = 0; half < 2; half++) {
            const int ml = mw * 32 + t * 16 + lg + half * 8;   // local m
            const int m  = mtile * 128 + ml;
            const float alpha = g_scale[m];
            const float rs    = g_rowsum[m];
            float* orow = out + (size_t)m * 4096;
            const int i0 = half * 2, i1 = half * 2 + 1;
            #pragma unroll
            for (int u = 0; u < 2; u++) {
                const int nl = nlb + u * 8;
                const int n  = ntile * 64 + nl;
                float v0 = (float)acc0[t][u][i0] + (float)sInt[ml * 68 + nl]     * inv254;
                float v1 = (float)acc0[t][u][i1] + (float)sInt[ml * 68 + nl + 1] * inv254;
                float2 o;
                o.x = __ldg(wscale + n)     * (alpha * v0) + __ldg(wbias + n)     * rs;
                o.y = __ldg(wscale + n + 1) * (alpha * v1) + __ldg(wbias + n + 1) * rs;
                *(float2*)(orow + n) = o;
            }
        }
    }
}

// ---------------- launch --------------------------------------------------------
extern "C" void kernel_launch(void* const* d_in, const int* in_sizes, int n_in,
                              void* d_out, int out_size) {
    (void)in_sizes; (void)n_in; (void)out_size;
    const float* x      = (const float*)d_in[0];   // [2,2048,4096]
    const float* weight = (const float*)d_in[1];   // [4096,4096]
    const float* wscale = (const float*)d_in[2];   // [4096,1]
    const float* wbias  = (const float*)d_in[3];   // [4096,1]
    float* out = (float*)d_out;

    cudaFuncSetAttribute(gemm_kernel, cudaFuncAttributeMaxDynamicSharedMemorySize,
                         (int)SMEM_DYN);

    prep_kernel<<<dim3(4096, 2), 256>>>(x, weight);
    gemm_kernel<<<dim3(64, 32), 512, SMEM_DYN>>>(wscale, wbias, out);
}